// round 16
// baseline (speedup 1.0000x reference)
#include <cuda_runtime.h>
#include <cstdint>
#include <cstddef>

// ---------------- constants ----------------
#define BATCH 64
#define NVARS 50
#define NHID 256
#define NIN 64
#define NEDGE 2450

// scratch layout (floats)
#define AGG_OFF  ((size_t)0)          // 3200*256
#define TR_OFF   ((size_t)819200)
#define TI_OFF   ((size_t)1638400)
#define TN_OFF   ((size_t)2457600)
#define GR_OFF   ((size_t)3276800)
#define GI_OFF   ((size_t)4096000)
#define GH_OFF   ((size_t)4915200)
#define P1_OFF   ((size_t)5734400)
#define SCRATCH_TOTAL ((size_t)6553600)

__device__ float g_scratch[SCRATCH_TOTAL];
// fc2 W fragments, bf16x2 words: [kk(3)][chunk(8)][4096 words]
#define WF_WORDS (3 * 8 * 4096)
__device__ uint32_t g_wf[WF_WORDS];
// Hr/Hs bf16x2 words: [kk(3)][half(2)][row(3200)][128 words]
#define HH_ROW_WORDS 128
#define HH_PLANE ((size_t)3200 * 128)
__device__ uint32_t g_hrhs[6 * 409600];

// fc1: As[2][2048] | Bs[2][4096] | bias[256]
#define BIG_SMEM_BYTES ((4096 + 8192 + 256) * 4)
// edge: Ws[8][4096] (full W resident) | As[2][2048] | bias[256]
#define EDGE_SMEM_BYTES ((32768 + 4096 + 256) * 4)
// gate (N128 split): As[2][2048] | Bs[2][2048]
#define GATE_SMEM_BYTES ((4096 + 4096) * 4)
// head (N128): Ahi[2048] Alo[2048] Bhi[2048] Blo[2048] bias[256]
#define HEAD_SMEM_BYTES ((2048 + 2048 + 2048 + 2048 + 256) * 4)

static __device__ __forceinline__ float tanha(float x) {
    float y; asm("tanh.approx.f32 %0, %1;" : "=f"(y) : "f"(x)); return y;
}
static __device__ __forceinline__ float sigm(float x) {
    return 1.0f / (1.0f + __expf(-x));
}
static __device__ __forceinline__ uint32_t pack_bf16(float lo, float hi) {
    uint32_t d; asm("cvt.rn.bf16x2.f32 %0, %1, %2;" : "=r"(d) : "f"(hi), "f"(lo));
    return d;
}
static __device__ __forceinline__ uint32_t add_bf16x2(uint32_t a, uint32_t b) {
    uint32_t d; asm("add.rn.bf16x2 %0, %1, %2;" : "=r"(d) : "r"(a), "r"(b));
    return d;
}
static __device__ __forceinline__ uint32_t tanh_bf16x2(uint32_t x) {
    uint32_t y; asm("tanh.approx.bf16x2 %0, %1;" : "=r"(y) : "r"(x));
    return y;
}
static __device__ __forceinline__ void split_bf16(float a, float b, uint32_t& hi, uint32_t& lo) {
    hi = pack_bf16(a, b);
    float ra = __uint_as_float(hi << 16);
    float rb = __uint_as_float(hi & 0xffff0000u);
    lo = pack_bf16(a - ra, b - rb);
}

#define CP16(dst, src) \
    asm volatile("cp.async.cg.shared.global [%0], [%1], 16;" :: "r"(dst), "l"(src) : "memory")
#define CP_COMMIT() asm volatile("cp.async.commit_group;" ::: "memory")
#define CP_WAIT(n)  asm volatile("cp.async.wait_group %0;" :: "n"(n) : "memory")

// m16n8k16 bf16 mma
static __device__ __forceinline__ void mma_bf16(float* d, const uint32_t* a,
                                                uint32_t b0, uint32_t b1) {
    asm volatile(
        "mma.sync.aligned.m16n8k16.row.col.f32.bf16.bf16.f32 "
        "{%0,%1,%2,%3}, {%4,%5,%6,%7}, {%8,%9}, {%0,%1,%2,%3};"
        : "+f"(d[0]), "+f"(d[1]), "+f"(d[2]), "+f"(d[3])
        : "r"(a[0]), "r"(a[1]), "r"(a[2]), "r"(a[3]), "r"(b0), "r"(b1));
}

// ---------------- generic NT GEMM core (fp32, small cases) ----------------
static __device__ __forceinline__ void gemm_core(
    const float* __restrict__ A, int lda,
    const float* __restrict__ Bw, int ldb,
    const float* __restrict__ bias,
    float* __restrict__ C,
    int N, int K, int bm, int bn, int act)
{
    __shared__ float As[16][65];
    __shared__ float Bs[16][68];

    int t = threadIdx.x;
    int ty = t >> 4;
    int tx = t & 15;

    float acc[8][4];
#pragma unroll
    for (int m = 0; m < 8; ++m)
#pragma unroll
        for (int n = 0; n < 4; ++n) acc[m][n] = 0.0f;

    for (int kb = 0; kb < K; kb += 16) {
        __syncthreads();
#pragma unroll
        for (int j = 0; j < 2; ++j) {
            int f4 = t * 2 + j;
            int row = f4 >> 2;
            int c = f4 & 3;
            float4 av = *(const float4*)&A[(size_t)(bm + row) * lda + kb + c * 4];
            As[c * 4 + 0][row] = av.x; As[c * 4 + 1][row] = av.y;
            As[c * 4 + 2][row] = av.z; As[c * 4 + 3][row] = av.w;
            float4 bv = *(const float4*)&Bw[(size_t)(bn + row) * ldb + kb + c * 4];
            Bs[c * 4 + 0][row] = bv.x; Bs[c * 4 + 1][row] = bv.y;
            Bs[c * 4 + 2][row] = bv.z; Bs[c * 4 + 3][row] = bv.w;
        }
        __syncthreads();
#pragma unroll
        for (int k2 = 0; k2 < 16; ++k2) {
            float a[8];
#pragma unroll
            for (int m = 0; m < 8; ++m) a[m] = As[k2][ty * 8 + m];
            float4 bv = *(const float4*)&Bs[k2][tx * 4];
            float b4[4] = {bv.x, bv.y, bv.z, bv.w};
#pragma unroll
            for (int m = 0; m < 8; ++m)
#pragma unroll
                for (int n = 0; n < 4; ++n) acc[m][n] += a[m] * b4[n];
        }
    }

#pragma unroll
    for (int m = 0; m < 8; ++m) {
        int row = bm + ty * 8 + m;
#pragma unroll
        for (int n = 0; n < 4; ++n) {
            int col = bn + tx * 4 + n;
            float v = acc[m][n];
            if (bias) v += bias[col];
            if (act == 3) v = fmaxf(v, 0.0f);
            C[(size_t)row * N + col] = v;
        }
    }
}

template <int ACT>
__global__ void __launch_bounds__(128) gemm_nt(
    const float* __restrict__ A, int lda,
    const float* __restrict__ Bw, int ldb,
    const float* __restrict__ bias,
    float* __restrict__ C, int N, int K)
{
    gemm_core(A, lda, Bw, ldb, bias, C, N, K, blockIdx.x * 64, blockIdx.y * 64, ACT);
}

// ---------------- pre-phase: proj(600) | zero(400) | fc2 w2frag(192) ----------------
__global__ void __launch_bounds__(128) pre_all(
    const float* __restrict__ inputs,
    const float* __restrict__ ir_w, const float* __restrict__ ii_w, const float* __restrict__ in_w,
    const float* __restrict__ ir_b, const float* __restrict__ ii_b, const float* __restrict__ in_b,
    const float* __restrict__ fc2w)
{
    int bid = blockIdx.x;
    int t = threadIdx.x;
    if (bid < 600) {
        int z = bid / 200, rem = bid - z * 200;
        int bm = (rem % 50) * 64, bn = (rem / 50) * 64;
        const float* w = (z == 0) ? ir_w : (z == 1) ? ii_w : in_w;
        const float* b = (z == 0) ? ir_b : (z == 1) ? ii_b : in_b;
        float* C = g_scratch + ((z == 0) ? TR_OFF : (z == 1) ? TI_OFF : TN_OFF);
        gemm_core(inputs, NIN, w, NIN, b, C, NHID, NIN, bm, bn, 0);
    } else if (bid < 1000) {
        int b2 = bid - 600;
        float4* p = (float4*)(g_scratch + AGG_OFF) + (size_t)b2 * 512 + t * 4;
        float4 z4 = make_float4(0.f, 0.f, 0.f, 0.f);
#pragma unroll
        for (int j = 0; j < 4; ++j) p[j] = z4;
    } else {
        int b2 = bid - 1000;
        int p0 = (b2 * 128 + t) * 4;
#pragma unroll
        for (int j = 0; j < 4; ++j) {
            int p = p0 + j;
            int lane = p & 31;
            int reg = (p >> 5) & 1;
            int tile = (p >> 6) & 63;
            int kstep = tile & 1, ntile = tile >> 1;
            int c = (p >> 12) & 7;
            int kk = p >> 15;
            int n = ntile * 8 + (lane >> 2);
            int k = c * 32 + kstep * 16 + reg * 8 + (lane & 3) * 2;
            const float* w = fc2w + (size_t)(kk + 1) * 65536 + (size_t)n * 256 + k;
            g_wf[p] = pack_bf16(w[0], w[1]);
        }
    }
}

// ---------------- fc1 via bf16 mma: Hr/Hs -> g_hrhs (bf16) ----------------
__global__ void __launch_bounds__(512, 1) fc1_mma(
    const float* __restrict__ hidden,
    const float* __restrict__ fc1w,
    const float* __restrict__ fc1b)
{
    extern __shared__ uint32_t dsm[];
    uint32_t* As_w0 = dsm;              // 2x2048
    uint32_t* Bs_w0 = dsm + 4096;       // 2x4096
    float* biasS = (float*)(dsm + 12288);

    int t = threadIdx.x;
    int wid = t >> 5, lid = t & 31;
    int m0 = blockIdx.x * 128;
    int kk = blockIdx.y, half = blockIdx.z, kt = kk + 1;

    if (t < 256) biasS[t] = half ? 0.0f : fc1b[kt * 256 + t];

    int grow = t >> 2, kq = t & 3;
    int kstep = kq >> 1, khalf = kq & 1;
    int mtile = grow >> 4, rl = grow & 15;
    uint32_t a_sts = (uint32_t)(((mtile * 2 + kstep) * 4) + (rl >> 3) + 2 * khalf) * 32
                     + (rl & 7) * 4;
    const float* Abase = hidden + (size_t)(m0 + grow) * 256 + kq * 8;

    int nn = t >> 1, kh = t & 1;
    const float* Bbase = fc1w + (size_t)kt * 131072 + (size_t)nn * 512 + half * 256 + kh * 16;
    int btile = (nn >> 3) * 2 + kh;
    uint32_t b_sts0 = (uint32_t)(btile * 2 + 0) * 32 + (nn & 7) * 4;
    uint32_t b_sts1 = (uint32_t)(btile * 2 + 1) * 32 + (nn & 7) * 4;

    int mw = wid >> 2, nw = wid & 3;

    float acc[2][8][4];
#pragma unroll
    for (int mt = 0; mt < 2; ++mt)
#pragma unroll
        for (int nt = 0; nt < 8; ++nt)
#pragma unroll
            for (int q = 0; q < 4; ++q) acc[mt][nt][q] = 0.0f;

    float4 av0, av1, bv0, bv1, bv2, bv3;

#define F1_LDG(c) do { \
        av0 = *(const float4*)(Abase + (c) * 32); \
        av1 = *(const float4*)(Abase + (c) * 32 + 4); \
        bv0 = *(const float4*)(Bbase + (c) * 32); \
        bv1 = *(const float4*)(Bbase + (c) * 32 + 4); \
        bv2 = *(const float4*)(Bbase + (c) * 32 + 8); \
        bv3 = *(const float4*)(Bbase + (c) * 32 + 12); \
    } while (0)

#define F1_STS(st) do { \
        uint4 xa; \
        xa.x = pack_bf16(av0.x, av0.y); xa.y = pack_bf16(av0.z, av0.w); \
        xa.z = pack_bf16(av1.x, av1.y); xa.w = pack_bf16(av1.z, av1.w); \
        *(uint4*)&As_w0[(st) * 2048 + a_sts] = xa; \
        uint4 w0, w1; \
        w0.x = pack_bf16(bv0.x, bv0.y); w0.y = pack_bf16(bv0.z, bv0.w); \
        w0.z = pack_bf16(bv1.x, bv1.y); w0.w = pack_bf16(bv1.z, bv1.w); \
        w1.x = pack_bf16(bv2.x, bv2.y); w1.y = pack_bf16(bv2.z, bv2.w); \
        w1.z = pack_bf16(bv3.x, bv3.y); w1.w = pack_bf16(bv3.z, bv3.w); \
        *(uint4*)&Bs_w0[(st) * 4096 + b_sts0] = w0; \
        *(uint4*)&Bs_w0[(st) * 4096 + b_sts1] = w1; \
    } while (0)

    F1_LDG(0);
    F1_STS(0);
    F1_LDG(1);

    for (int c = 0; c < 8; ++c) {
        int st = c & 1;
        __syncthreads();
        const uint32_t* Asb = As_w0 + st * 2048;
        const uint32_t* Bsb = Bs_w0 + st * 4096;
#pragma unroll
        for (int ks = 0; ks < 2; ++ks) {
            uint32_t a[2][4];
#pragma unroll
            for (int mt = 0; mt < 2; ++mt) {
                int tile = (mw * 2 + mt) * 2 + ks;
#pragma unroll
                for (int rg = 0; rg < 4; ++rg)
                    a[mt][rg] = Asb[(tile * 4 + rg) * 32 + lid];
            }
#pragma unroll
            for (int nt = 0; nt < 8; ++nt) {
                int tile = (nw * 8 + nt) * 2 + ks;
                uint32_t b0 = Bsb[(tile * 2 + 0) * 32 + lid];
                uint32_t b1 = Bsb[(tile * 2 + 1) * 32 + lid];
                mma_bf16(acc[0][nt], a[0], b0, b1);
                mma_bf16(acc[1][nt], a[1], b0, b1);
            }
        }
        if (c < 7) {
            F1_STS((c + 1) & 1);
            if (c < 6) F1_LDG(c + 2);
        }
    }

    int lq = lid & 3, lr = lid >> 2;
    uint32_t* outp = g_hrhs + (size_t)(kk * 2 + half) * HH_PLANE;
#pragma unroll
    for (int mt = 0; mt < 2; ++mt)
#pragma unroll
        for (int rh = 0; rh < 2; ++rh) {
            int row = m0 + mw * 32 + mt * 16 + rh * 8 + lr;
#pragma unroll
            for (int nt = 0; nt < 8; ++nt) {
                int col = nw * 64 + nt * 8 + lq * 2;
                float v0 = acc[mt][nt][rh * 2 + 0] + biasS[col];
                float v1 = acc[mt][nt][rh * 2 + 1] + biasS[col + 1];
                outp[(size_t)row * HH_ROW_WORDS + (col >> 1)] = pack_bf16(v0, v1);
            }
        }
#undef F1_LDG
#undef F1_STS
}

// ---------------- gate GEMMs via bf16 mma (N128 split, grid (25,3,2)) ----------------
// 512 threads, 16 warps = 4 m-warps (M32) x 4 n-warps (N32).
__global__ void __launch_bounds__(512, 1) gate_mma(
    const float* __restrict__ hr_w, const float* __restrict__ hi_w, const float* __restrict__ hh_w)
{
    extern __shared__ uint32_t dsm[];
    uint32_t* As_w0 = dsm;              // 2x2048
    uint32_t* Bs_w0 = dsm + 4096;       // 2x2048

    int t = threadIdx.x;
    int wid = t >> 5, lid = t & 31;
    int m0 = blockIdx.x * 128;
    int z = blockIdx.y;
    int nh = blockIdx.z;
    const float* W = (z == 0) ? hr_w : (z == 1) ? hi_w : hh_w;
    float* C = g_scratch + ((z == 0) ? GR_OFF : (z == 1) ? GI_OFF : GH_OFF);
    const float* A = g_scratch + AGG_OFF;

    int grow = t >> 2, kq = t & 3;
    int kstep = kq >> 1, khalf = kq & 1;
    int mtile = grow >> 4, rl = grow & 15;
    uint32_t a_sts = (uint32_t)(((mtile * 2 + kstep) * 4) + (rl >> 3) + 2 * khalf) * 32
                     + (rl & 7) * 4;
    const float* Abase = A + (size_t)(m0 + grow) * 256 + kq * 8;

    // B: 128 rows of W (nh half); each thread = (nn, khb, sub) -> 8 floats
    int nn = t >> 2, khb = (t >> 1) & 1, sub = t & 1;
    const float* Bbase = W + (size_t)(nh * 128 + nn) * 256 + khb * 16 + sub * 8;
    int btile = (nn >> 3) * 2 + khb;
    uint32_t b_sts = (uint32_t)(btile * 2 + sub) * 32 + (nn & 7) * 4;

    int mw = wid >> 2, nw = wid & 3;

    float acc[2][4][4];
#pragma unroll
    for (int mt = 0; mt < 2; ++mt)
#pragma unroll
        for (int nt = 0; nt < 4; ++nt)
#pragma unroll
            for (int q = 0; q < 4; ++q) acc[mt][nt][q] = 0.0f;

    float4 av0, av1, bv0, bv1;

#define G_LDG(c) do { \
        av0 = *(const float4*)(Abase + (c) * 32); \
        av1 = *(const float4*)(Abase + (c) * 32 + 4); \
        bv0 = *(const float4*)(Bbase + (c) * 32); \
        bv1 = *(const float4*)(Bbase + (c) * 32 + 4); \
    } while (0)

#define G_STS(st) do { \
        uint4 xa; \
        xa.x = pack_bf16(av0.x, av0.y); xa.y = pack_bf16(av0.z, av0.w); \
        xa.z = pack_bf16(av1.x, av1.y); xa.w = pack_bf16(av1.z, av1.w); \
        *(uint4*)&As_w0[(st) * 2048 + a_sts] = xa; \
        uint4 wv; \
        wv.x = pack_bf16(bv0.x, bv0.y); wv.y = pack_bf16(bv0.z, bv0.w); \
        wv.z = pack_bf16(bv1.x, bv1.y); wv.w = pack_bf16(bv1.z, bv1.w); \
        *(uint4*)&Bs_w0[(st) * 2048 + b_sts] = wv; \
    } while (0)

    G_LDG(0);
    G_STS(0);
    G_LDG(1);

    for (int c = 0; c < 8; ++c) {
        int st = c & 1;
        __syncthreads();
        const uint32_t* Asb = As_w0 + st * 2048;
        const uint32_t* Bsb = Bs_w0 + st * 2048;
#pragma unroll
        for (int ks = 0; ks < 2; ++ks) {
            uint32_t a[2][4];
#pragma unroll
            for (int mt = 0; mt < 2; ++mt) {
                int tile = (mw * 2 + mt) * 2 + ks;
#pragma unroll
                for (int rg = 0; rg < 4; ++rg)
                    a[mt][rg] = Asb[(tile * 4 + rg) * 32 + lid];
            }
#pragma unroll
            for (int nt = 0; nt < 4; ++nt) {
                int tile = (nw * 4 + nt) * 2 + ks;
                uint32_t b0 = Bsb[(tile * 2 + 0) * 32 + lid];
                uint32_t b1 = Bsb[(tile * 2 + 1) * 32 + lid];
                mma_bf16(acc[0][nt], a[0], b0, b1);
                mma_bf16(acc[1][nt], a[1], b0, b1);
            }
        }
        if (c < 7) {
            G_STS((c + 1) & 1);
            if (c < 6) G_LDG(c + 2);
        }
    }

    int lq = lid & 3, lr = lid >> 2;
#pragma unroll
    for (int mt = 0; mt < 2; ++mt)
#pragma unroll
        for (int rh = 0; rh < 2; ++rh) {
            int row = m0 + mw * 32 + mt * 16 + rh * 8 + lr;
#pragma unroll
            for (int nt = 0; nt < 4; ++nt) {
                int col = nh * 128 + nw * 32 + nt * 8 + lq * 2;
                C[(size_t)row * 256 + col]     = acc[mt][nt][rh * 2 + 0];
                C[(size_t)row * 256 + col + 1] = acc[mt][nt][rh * 2 + 1];
            }
        }
#undef G_LDG
#undef G_STS
}

// ---------------- GRU elementwise ----------------
__global__ void gru_elem(const float* __restrict__ hidden, float* __restrict__ new_hidden) {
    const float* tr = g_scratch + TR_OFF;
    const float* ti = g_scratch + TI_OFF;
    const float* tn = g_scratch + TN_OFF;
    const float* gr = g_scratch + GR_OFF;
    const float* gi = g_scratch + GI_OFF;
    const float* gh = g_scratch + GH_OFF;
    int total = BATCH * NVARS * NHID;
    for (int idx = blockIdx.x * blockDim.x + threadIdx.x; idx < total; idx += gridDim.x * blockDim.x) {
        float r_ = sigm(gr[idx] + tr[idx]);
        float i_ = sigm(gi[idx] + ti[idx]);
        float n_ = tanha(tn[idx] + r_ * gh[idx]);
        new_hidden[idx] = (1.0f - i_) * n_ + i_ * hidden[idx];
    }
}

// ---------------- head GEMM via split-bf16 (3-MMA), N128 per block, grid (25,2) ----------------
__global__ void __launch_bounds__(512, 1) head_mma(
    const float* __restrict__ Ain, const float* __restrict__ W,
    const float* __restrict__ bias, float* __restrict__ C)
{
    extern __shared__ uint32_t dsm[];
    uint32_t* Ahi = dsm;
    uint32_t* Alo = dsm + 2048;
    uint32_t* Bhi = dsm + 4096;
    uint32_t* Blo = dsm + 6144;
    float* biasS = (float*)(dsm + 8192);

    int t = threadIdx.x;
    int wid = t >> 5, lid = t & 31;
    int m0 = blockIdx.x * 128;
    int nh = blockIdx.y;

    if (t < 256) biasS[t] = bias[t];

    int grow = t >> 2, kq = t & 3;
    int kstep = kq >> 1, khalf = kq & 1;
    int mtile = grow >> 4, rl = grow & 15;
    uint32_t a_sts = (uint32_t)(((mtile * 2 + kstep) * 4) + (rl >> 3) + 2 * khalf) * 32
                     + (rl & 7) * 4;
    const float* Abase = Ain + (size_t)(m0 + grow) * 256 + kq * 8;

    int nn = t >> 2, khb = (t >> 1) & 1, sub = t & 1;
    const float* Bbase = W + (size_t)(nh * 128 + nn) * 256 + khb * 16 + sub * 8;
    int btile = (nn >> 3) * 2 + khb;
    uint32_t b_sts = (uint32_t)(btile * 2 + sub) * 32 + (nn & 7) * 4;

    int mw = wid >> 2, nw = wid & 3;

    float acc[2][4][4];
#pragma unroll
    for (int mt = 0; mt < 2; ++mt)
#pragma unroll
        for (int nt = 0; nt < 4; ++nt)
#pragma unroll
            for (int q = 0; q < 4; ++q) acc[mt][nt][q] = 0.0f;

    float4 av0, av1, bv0, bv1;

#define H_LDG(c) do { \
        av0 = *(const float4*)(Abase + (c) * 32); \
        av1 = *(const float4*)(Abase + (c) * 32 + 4); \
        bv0 = *(const float4*)(Bbase + (c) * 32); \
        bv1 = *(const float4*)(Bbase + (c) * 32 + 4); \
    } while (0)

#define H_STS() do { \
        uint4 xh, xl; \
        split_bf16(av0.x, av0.y, xh.x, xl.x); \
        split_bf16(av0.z, av0.w, xh.y, xl.y); \
        split_bf16(av1.x, av1.y, xh.z, xl.z); \
        split_bf16(av1.z, av1.w, xh.w, xl.w); \
        *(uint4*)&Ahi[a_sts] = xh; \
        *(uint4*)&Alo[a_sts] = xl; \
        uint4 wh, wl; \
        split_bf16(bv0.x, bv0.y, wh.x, wl.x); \
        split_bf16(bv0.z, bv0.w, wh.y, wl.y); \
        split_bf16(bv1.x, bv1.y, wh.z, wl.z); \
        split_bf16(bv1.z, bv1.w, wh.w, wl.w); \
        *(uint4*)&Bhi[b_sts] = wh; \
        *(uint4*)&Blo[b_sts] = wl; \
    } while (0)

    H_LDG(0);

    for (int c = 0; c < 8; ++c) {
        __syncthreads();
        H_STS();
        __syncthreads();
        if (c < 7) H_LDG(c + 1);
#pragma unroll
        for (int ks = 0; ks < 2; ++ks) {
            uint32_t ah[2][4], al[2][4];
#pragma unroll
            for (int mt = 0; mt < 2; ++mt) {
                int tile = (mw * 2 + mt) * 2 + ks;
#pragma unroll
                for (int rg = 0; rg < 4; ++rg) {
                    ah[mt][rg] = Ahi[(tile * 4 + rg) * 32 + lid];
                    al[mt][rg] = Alo[(tile * 4 + rg) * 32 + lid];
                }
            }
#pragma unroll
            for (int nt = 0; nt < 4; ++nt) {
                int tile = (nw * 4 + nt) * 2 + ks;
                uint32_t bh0 = Bhi[(tile * 2 + 0) * 32 + lid];
                uint32_t bh1 = Bhi[(tile * 2 + 1) * 32 + lid];
                uint32_t bl0 = Blo[(tile * 2 + 0) * 32 + lid];
                uint32_t bl1 = Blo[(tile * 2 + 1) * 32 + lid];
#pragma unroll
                for (int mt = 0; mt < 2; ++mt) {
                    mma_bf16(acc[mt][nt], ah[mt], bh0, bh1);
                    mma_bf16(acc[mt][nt], ah[mt], bl0, bl1);
                    mma_bf16(acc[mt][nt], al[mt], bh0, bh1);
                }
            }
        }
    }

    int lq = lid & 3, lr = lid >> 2;
#pragma unroll
    for (int mt = 0; mt < 2; ++mt)
#pragma unroll
        for (int rh = 0; rh < 2; ++rh) {
            int row = m0 + mw * 32 + mt * 16 + rh * 8 + lr;
#pragma unroll
            for (int nt = 0; nt < 4; ++nt) {
                int colg = nh * 128 + nw * 32 + nt * 8 + lq * 2;
                float v0 = fmaxf(acc[mt][nt][rh * 2 + 0] + biasS[colg], 0.0f);
                float v1 = fmaxf(acc[mt][nt][rh * 2 + 1] + biasS[colg + 1], 0.0f);
                C[(size_t)row * 256 + colg]     = v0;
                C[(size_t)row * 256 + colg + 1] = v1;
            }
        }
#undef H_LDG
#undef H_STS
}

// ---------------- bf16 mma.sync edge kernel: W resident in smem, 5 receivers/block ----------------
// grid (25, 10, 3): x = m-tile (128 rows), y = receiver group (r = 5y..5y+4), z = kk.
__global__ void __launch_bounds__(512, 1) edge_mma(
    const float* __restrict__ edges,
    const float* __restrict__ fc2b)
{
    extern __shared__ uint32_t dsm[];
    uint32_t* Ws = dsm;                 // 8x4096 (full W, resident)
    uint32_t* As_w0 = dsm + 32768;      // 2x2048
    float* biasS = (float*)(dsm + 32768 + 4096);

    int t = threadIdx.x;
    int wid = t >> 5, lid = t & 31;
    int m0 = blockIdx.x * 128;
    int r0 = blockIdx.y * 5;
    int kk = blockIdx.z, kt = kk + 1;

    const uint32_t* HRw = g_hrhs + (size_t)(kk * 2 + 0) * HH_PLANE;
    const uint32_t* HSw = g_hrhs + (size_t)(kk * 2 + 1) * HH_PLANE;

    if (t < 256) biasS[t] = fc2b[kt * 256 + t];

    int grow = t >> 2, kq = t & 3;
    int kstep = kq >> 1, khalf = kq & 1;
    int gg = m0 + grow;
    int gb = gg / 50, gi = gg - gb * 50;
    uint32_t hs_base = (uint32_t)(gb * 50 + gi) * HH_ROW_WORDS + kq * 4;
    int mtile = grow >> 4, rl = grow & 15;
    uint32_t a_sts = (uint32_t)(((mtile * 2 + kstep) * 4) + (rl >> 3) + 2 * khalf) * 32
                     + (rl & 7) * 4;
    const uint32_t* wf = g_wf + (size_t)kk * 32768 + t * 8;
    uint32_t ws_u32 = (uint32_t)__cvta_generic_to_shared(Ws) + t * 8 * 4;

    int mw = wid >> 2, nw = wid & 3;

    // issue the full W load (8 chunk-groups, committed in order)
#pragma unroll
    for (int c = 0; c < 8; ++c) {
        uint32_t d = ws_u32 + c * 4096 * 4;
        CP16(d, wf + c * 4096);
        CP16(d + 16, wf + c * 4096 + 4);
        CP_COMMIT();
    }

    // epilogue row mapping (r-independent)
    int lq = lid & 3, lr = lid >> 2;
    int base_row = mw * 32;
    int bfirst = (m0 + base_row) / 50;
    int blast = (m0 + base_row + 31) / 50;
    int has1 = (blast != bfirst);
    int erow_b[4], erow_i[4], sg[4];
#pragma unroll
    for (int j = 0; j < 4; ++j) {
        int mt = j >> 1, rh = j & 1;
        int g = m0 + base_row + mt * 16 + rh * 8 + lr;
        erow_b[j] = g / 50;
        erow_i[j] = g - erow_b[j] * 50;
        sg[j] = erow_b[j] - bfirst;
    }

    uint4 hv, sv;
    uint32_t hr_base;

#define LDG_A(c) do { \
        hv = *(const uint4*)(HRw + hr_base + (c) * 16); \
        sv = *(const uint4*)(HSw + hs_base + (c) * 16); \
    } while (0)

#define STS_A(st) do { \
        uint4 xa; \
        xa.x = tanh_bf16x2(add_bf16x2(hv.x, sv.x)); \
        xa.y = tanh_bf16x2(add_bf16x2(hv.y, sv.y)); \
        xa.z = tanh_bf16x2(add_bf16x2(hv.z, sv.z)); \
        xa.w = tanh_bf16x2(add_bf16x2(hv.w, sv.w)); \
        *(uint4*)&As_w0[(st) * 2048 + a_sts] = xa; \
    } while (0)

    for (int rl5 = 0; rl5 < 5; ++rl5) {
        int r = r0 + rl5;
        hr_base = (uint32_t)(gb * 50 + r) * HH_ROW_WORDS + kq * 4;

        float acc[2][8][4];
#pragma unroll
        for (int mt = 0; mt < 2; ++mt)
#pragma unroll
            for (int nt = 0; nt < 8; ++nt)
#pragma unroll
                for (int q = 0; q < 4; ++q) acc[mt][nt][q] = 0.0f;

        LDG_A(0);
        STS_A(0);
        LDG_A(1);

#pragma unroll
        for (int c = 0; c < 8; ++c) {
            if (rl5 == 0) {
                switch (c) {
                    case 0: CP_WAIT(7); break;
                    case 1: CP_WAIT(6); break;
                    case 2: CP_WAIT(5); break;
                    case 3: CP_WAIT(4); break;
                    case 4: CP_WAIT(3); break;
                    case 5: CP_WAIT(2); break;
                    case 6: CP_WAIT(1); break;
                    case 7: CP_WAIT(0); break;
                }
            }
            __syncthreads();
            const uint32_t* Asb = As_w0 + (c & 1) * 2048;
            const uint32_t* Bsb = Ws + c * 4096;
#pragma unroll
            for (int ks = 0; ks < 2; ++ks) {
                uint32_t a[2][4];
#pragma unroll
                for (int mt = 0; mt < 2; ++mt) {
                    int tile = (mw * 2 + mt) * 2 + ks;
#pragma unroll
                    for (int rg = 0; rg < 4; ++rg)
                        a[mt][rg] = Asb[(tile * 4 + rg) * 32 + lid];
                }
#pragma unroll
                for (int nt = 0; nt < 8; ++nt) {
                    int tile = (nw * 8 + nt) * 2 + ks;
                    uint32_t b0 = Bsb[(tile * 2 + 0) * 32 + lid];
                    uint32_t b1 = Bsb[(tile * 2 + 1) * 32 + lid];
                    mma_bf16(acc[0][nt], a[0], b0, b1);
                    mma_bf16(acc[1][nt], a[1], b0, b1);
                }
            }
            if (c < 7) {
                STS_A((c + 1) & 1);
                if (c < 6) LDG_A(c + 2);
            }
        }

        // epilogue for this r
        float wgt[4];
#pragma unroll
        for (int j = 0; j < 4; ++j) {
            float w = 0.0f;
            int i = erow_i[j];
            if (i != r) {
                int e = i * 49 + r - (i < r ? 1 : 0);
                w = __ldg(&edges[((size_t)erow_b[j] * NEDGE + e) * 4 + kt]) * (1.0f / 147.0f);
            }
            wgt[j] = w;
        }

        float* agg0 = g_scratch + AGG_OFF + ((size_t)(bfirst * 50 + r)) * 256;

#pragma unroll
        for (int nt = 0; nt < 8; ++nt) {
            int colg = nw * 64 + nt * 8 + lq * 2;
            float b0 = biasS[colg], b1 = biasS[colg + 1];
            float c0[2] = {0.0f, 0.0f}, c1[2] = {0.0f, 0.0f};
#pragma unroll
            for (int j = 0; j < 4; ++j) {
                int mt = j >> 1, rh = j & 1;
                float t0 = tanha(acc[mt][nt][rh * 2 + 0] + b0) * wgt[j];
                float t1 = tanha(acc[mt][nt][rh * 2 + 1] + b1) * wgt[j];
                if (sg[j] == 0) { c0[0] += t0; c1[0] += t1; }
                else            { c0[1] += t0; c1[1] += t1; }
            }
#pragma unroll
            for (int o = 4; o <= 16; o <<= 1) {
                c0[0] += __shfl_xor_sync(0xffffffffu, c0[0], o);
                c1[0] += __shfl_xor_sync(0xffffffffu, c1[0], o);
                if (has1) {
                    c0[1] += __shfl_xor_sync(0xffffffffu, c0[1], o);
                    c1[1] += __shfl_xor_sync(0xffffffffu, c1[1], o);
                }
            }
            if (lid < 4) {
                atomicAdd(&agg0[colg], c0[0]);
                atomicAdd(&agg0[colg + 1], c1[0]);
                if (has1) {
                    atomicAdd(&agg0[12800 + colg], c0[1]);
                    atomicAdd(&agg0[12800 + colg + 1], c1[1]);
                }
            }
        }
    }
#undef LDG_A
#undef STS_A
}

// ---------------- launch ----------------
extern "C" void kernel_launch(void* const* d_in, const int* in_sizes, int n_in,
                              void* d_out, int out_size) {
    const float* inputs = (const float*)d_in[0];
    const float* hidden = (const float*)d_in[1];
    const float* edges  = (const float*)d_in[2];
    const float* fc1w   = (const float*)d_in[3];
    const float* fc1b   = (const float*)d_in[4];
    const float* fc2w   = (const float*)d_in[5];
    const float* fc2b   = (const float*)d_in[6];
    const float* hr_w   = (const float*)d_in[7];
    const float* hi_w   = (const float*)d_in[8];
    const float* hh_w   = (const float*)d_in[9];
    const float* ir_w   = (const float*)d_in[10];
    const float* ir_b   = (const float*)d_in[11];
    const float* ii_w   = (const float*)d_in[12];
    const float* ii_b   = (const float*)d_in[13];
    const float* in_w   = (const float*)d_in[14];
    const float* in_b   = (const float*)d_in[15];
    const float* of1_w  = (const float*)d_in[16];
    const float* of1_b  = (const float*)d_in[17];
    const float* of2_w  = (const float*)d_in[18];
    const float* of2_b  = (const float*)d_in[19];
    const float* mu_w   = (const float*)d_in[20];
    const float* mu_b   = (const float*)d_in[21];

    float* out = (float*)d_out;
    float* out_mu   = out;               // [64,50,64]
    float* out_nh   = out + 204800;      // [64,50,256]
    float* out_pred = out + 1024000;     // [64,50,256]

    float* S = nullptr;
    cudaGetSymbolAddress((void**)&S, g_scratch);

    cudaFuncSetAttribute(edge_mma, cudaFuncAttributeMaxDynamicSharedMemorySize, EDGE_SMEM_BYTES);
    cudaFuncSetAttribute(fc1_mma, cudaFuncAttributeMaxDynamicSharedMemorySize, BIG_SMEM_BYTES);
    cudaFuncSetAttribute(gate_mma, cudaFuncAttributeMaxDynamicSharedMemorySize, GATE_SMEM_BYTES);
    cudaFuncSetAttribute(head_mma, cudaFuncAttributeMaxDynamicSharedMemorySize, HEAD_SMEM_BYTES);

    const int M = BATCH * NVARS;  // 3200

    fc1_mma<<<dim3(25, 3, 2), 512, BIG_SMEM_BYTES>>>(hidden, fc1w, fc1b);
    pre_all<<<1192, 128>>>(inputs, ir_w, ii_w, in_w, ir_b, ii_b, in_b, fc2w);

    edge_mma<<<dim3(25, 10, 3), 512, EDGE_SMEM_BYTES>>>(edges, fc2b);

    gate_mma<<<dim3(25, 3, 2), 512, GATE_SMEM_BYTES>>>(hr_w, hi_w, hh_w);
    gru_elem<<<800, 256>>>(hidden, out_nh);

    head_mma<<<dim3(25, 2), 512, HEAD_SMEM_BYTES>>>(out_nh, of1_w, of1_b, S + P1_OFF);
    head_mma<<<dim3(25, 2), 512, HEAD_SMEM_BYTES>>>(S + P1_OFF, of2_w, of2_b, out_pred);

    gemm_nt<0><<<dim3(M / 64, 1), 128>>>(out_pred, NHID, mu_w, NHID, mu_b, out_mu, NIN, NHID);
}

// round 17
// speedup vs baseline: 1.0041x; 1.0041x over previous
#include <cuda_runtime.h>
#include <cstdint>
#include <cstddef>

// ---------------- constants ----------------
#define BATCH 64
#define NVARS 50
#define NHID 256
#define NIN 64
#define NEDGE 2450

// scratch layout (floats)
#define AGG_OFF  ((size_t)0)          // 3200*256
#define TR_OFF   ((size_t)819200)
#define TI_OFF   ((size_t)1638400)
#define TN_OFF   ((size_t)2457600)
#define GR_OFF   ((size_t)3276800)
#define GI_OFF   ((size_t)4096000)
#define GH_OFF   ((size_t)4915200)
#define P1_OFF   ((size_t)5734400)
#define SCRATCH_TOTAL ((size_t)6553600)

__device__ float g_scratch[SCRATCH_TOTAL];
// fc2 W fragments, bf16x2 words: [kk(3)][chunk(8)][4096 words]
#define WF_WORDS (3 * 8 * 4096)
__device__ uint32_t g_wf[WF_WORDS];
// Hr/Hs bf16x2 words: [kk(3)][half(2)][row(3200)][128 words]
#define HH_ROW_WORDS 128
#define HH_PLANE ((size_t)3200 * 128)
__device__ uint32_t g_hrhs[6 * 409600];

// fc1/gate: As[2][2048] | Bs[2][4096] | bias[256]
#define BIG_SMEM_BYTES ((4096 + 8192 + 256) * 4)
// edge: Ws[8][4096] (full W resident) | As[2][2048] | bias[256]
#define EDGE_SMEM_BYTES ((32768 + 4096 + 256) * 4)
// head (N128): Ahi[2048] Alo[2048] Bhi[2048] Blo[2048] bias[256]
#define HEAD_SMEM_BYTES ((2048 + 2048 + 2048 + 2048 + 256) * 4)

static __device__ __forceinline__ float tanha(float x) {
    float y; asm("tanh.approx.f32 %0, %1;" : "=f"(y) : "f"(x)); return y;
}
static __device__ __forceinline__ float sigm(float x) {
    return 1.0f / (1.0f + __expf(-x));
}
static __device__ __forceinline__ uint32_t pack_bf16(float lo, float hi) {
    uint32_t d; asm("cvt.rn.bf16x2.f32 %0, %1, %2;" : "=r"(d) : "f"(hi), "f"(lo));
    return d;
}
static __device__ __forceinline__ uint32_t add_bf16x2(uint32_t a, uint32_t b) {
    uint32_t d; asm("add.rn.bf16x2 %0, %1, %2;" : "=r"(d) : "r"(a), "r"(b));
    return d;
}
static __device__ __forceinline__ uint32_t tanh_bf16x2(uint32_t x) {
    uint32_t y; asm("tanh.approx.bf16x2 %0, %1;" : "=r"(y) : "r"(x));
    return y;
}
static __device__ __forceinline__ void split_bf16(float a, float b, uint32_t& hi, uint32_t& lo) {
    hi = pack_bf16(a, b);
    float ra = __uint_as_float(hi << 16);
    float rb = __uint_as_float(hi & 0xffff0000u);
    lo = pack_bf16(a - ra, b - rb);
}

#define CP16(dst, src) \
    asm volatile("cp.async.cg.shared.global [%0], [%1], 16;" :: "r"(dst), "l"(src) : "memory")
#define CP_COMMIT() asm volatile("cp.async.commit_group;" ::: "memory")
#define CP_WAIT(n)  asm volatile("cp.async.wait_group %0;" :: "n"(n) : "memory")

// m16n8k16 bf16 mma
static __device__ __forceinline__ void mma_bf16(float* d, const uint32_t* a,
                                                uint32_t b0, uint32_t b1) {
    asm volatile(
        "mma.sync.aligned.m16n8k16.row.col.f32.bf16.bf16.f32 "
        "{%0,%1,%2,%3}, {%4,%5,%6,%7}, {%8,%9}, {%0,%1,%2,%3};"
        : "+f"(d[0]), "+f"(d[1]), "+f"(d[2]), "+f"(d[3])
        : "r"(a[0]), "r"(a[1]), "r"(a[2]), "r"(a[3]), "r"(b0), "r"(b1));
}

// ---------------- generic NT GEMM core (fp32, small cases) ----------------
static __device__ __forceinline__ void gemm_core(
    const float* __restrict__ A, int lda,
    const float* __restrict__ Bw, int ldb,
    const float* __restrict__ bias,
    float* __restrict__ C,
    int N, int K, int bm, int bn, int act)
{
    __shared__ float As[16][65];
    __shared__ float Bs[16][68];

    int t = threadIdx.x;
    int ty = t >> 4;
    int tx = t & 15;

    float acc[8][4];
#pragma unroll
    for (int m = 0; m < 8; ++m)
#pragma unroll
        for (int n = 0; n < 4; ++n) acc[m][n] = 0.0f;

    for (int kb = 0; kb < K; kb += 16) {
        __syncthreads();
#pragma unroll
        for (int j = 0; j < 2; ++j) {
            int f4 = t * 2 + j;
            int row = f4 >> 2;
            int c = f4 & 3;
            float4 av = *(const float4*)&A[(size_t)(bm + row) * lda + kb + c * 4];
            As[c * 4 + 0][row] = av.x; As[c * 4 + 1][row] = av.y;
            As[c * 4 + 2][row] = av.z; As[c * 4 + 3][row] = av.w;
            float4 bv = *(const float4*)&Bw[(size_t)(bn + row) * ldb + kb + c * 4];
            Bs[c * 4 + 0][row] = bv.x; Bs[c * 4 + 1][row] = bv.y;
            Bs[c * 4 + 2][row] = bv.z; Bs[c * 4 + 3][row] = bv.w;
        }
        __syncthreads();
#pragma unroll
        for (int k2 = 0; k2 < 16; ++k2) {
            float a[8];
#pragma unroll
            for (int m = 0; m < 8; ++m) a[m] = As[k2][ty * 8 + m];
            float4 bv = *(const float4*)&Bs[k2][tx * 4];
            float b4[4] = {bv.x, bv.y, bv.z, bv.w};
#pragma unroll
            for (int m = 0; m < 8; ++m)
#pragma unroll
                for (int n = 0; n < 4; ++n) acc[m][n] += a[m] * b4[n];
        }
    }

#pragma unroll
    for (int m = 0; m < 8; ++m) {
        int row = bm + ty * 8 + m;
#pragma unroll
        for (int n = 0; n < 4; ++n) {
            int col = bn + tx * 4 + n;
            float v = acc[m][n];
            if (bias) v += bias[col];
            if (act == 3) v = fmaxf(v, 0.0f);
            C[(size_t)row * N + col] = v;
        }
    }
}

template <int ACT>
__global__ void __launch_bounds__(128) gemm_nt(
    const float* __restrict__ A, int lda,
    const float* __restrict__ Bw, int ldb,
    const float* __restrict__ bias,
    float* __restrict__ C, int N, int K)
{
    gemm_core(A, lda, Bw, ldb, bias, C, N, K, blockIdx.x * 64, blockIdx.y * 64, ACT);
}

// ---------------- pre-phase: proj(600) | zero(400) | fc2 w2frag(192) ----------------
__global__ void __launch_bounds__(128) pre_all(
    const float* __restrict__ inputs,
    const float* __restrict__ ir_w, const float* __restrict__ ii_w, const float* __restrict__ in_w,
    const float* __restrict__ ir_b, const float* __restrict__ ii_b, const float* __restrict__ in_b,
    const float* __restrict__ fc2w)
{
    int bid = blockIdx.x;
    int t = threadIdx.x;
    if (bid < 600) {
        int z = bid / 200, rem = bid - z * 200;
        int bm = (rem % 50) * 64, bn = (rem / 50) * 64;
        const float* w = (z == 0) ? ir_w : (z == 1) ? ii_w : in_w;
        const float* b = (z == 0) ? ir_b : (z == 1) ? ii_b : in_b;
        float* C = g_scratch + ((z == 0) ? TR_OFF : (z == 1) ? TI_OFF : TN_OFF);
        gemm_core(inputs, NIN, w, NIN, b, C, NHID, NIN, bm, bn, 0);
    } else if (bid < 1000) {
        int b2 = bid - 600;
        float4* p = (float4*)(g_scratch + AGG_OFF) + (size_t)b2 * 512 + t * 4;
        float4 z4 = make_float4(0.f, 0.f, 0.f, 0.f);
#pragma unroll
        for (int j = 0; j < 4; ++j) p[j] = z4;
    } else {
        int b2 = bid - 1000;
        int p0 = (b2 * 128 + t) * 4;
#pragma unroll
        for (int j = 0; j < 4; ++j) {
            int p = p0 + j;
            int lane = p & 31;
            int reg = (p >> 5) & 1;
            int tile = (p >> 6) & 63;
            int kstep = tile & 1, ntile = tile >> 1;
            int c = (p >> 12) & 7;
            int kk = p >> 15;
            int n = ntile * 8 + (lane >> 2);
            int k = c * 32 + kstep * 16 + reg * 8 + (lane & 3) * 2;
            const float* w = fc2w + (size_t)(kk + 1) * 65536 + (size_t)n * 256 + k;
            g_wf[p] = pack_bf16(w[0], w[1]);
        }
    }
}

// ---------------- fc1 via bf16 mma: Hr/Hs -> g_hrhs (bf16) ----------------
__global__ void __launch_bounds__(512, 1) fc1_mma(
    const float* __restrict__ hidden,
    const float* __restrict__ fc1w,
    const float* __restrict__ fc1b)
{
    extern __shared__ uint32_t dsm[];
    uint32_t* As_w0 = dsm;              // 2x2048
    uint32_t* Bs_w0 = dsm + 4096;       // 2x4096
    float* biasS = (float*)(dsm + 12288);

    int t = threadIdx.x;
    int wid = t >> 5, lid = t & 31;
    int m0 = blockIdx.x * 128;
    int kk = blockIdx.y, half = blockIdx.z, kt = kk + 1;

    if (t < 256) biasS[t] = half ? 0.0f : fc1b[kt * 256 + t];

    int grow = t >> 2, kq = t & 3;
    int kstep = kq >> 1, khalf = kq & 1;
    int mtile = grow >> 4, rl = grow & 15;
    uint32_t a_sts = (uint32_t)(((mtile * 2 + kstep) * 4) + (rl >> 3) + 2 * khalf) * 32
                     + (rl & 7) * 4;
    const float* Abase = hidden + (size_t)(m0 + grow) * 256 + kq * 8;

    int nn = t >> 1, kh = t & 1;
    const float* Bbase = fc1w + (size_t)kt * 131072 + (size_t)nn * 512 + half * 256 + kh * 16;
    int btile = (nn >> 3) * 2 + kh;
    uint32_t b_sts0 = (uint32_t)(btile * 2 + 0) * 32 + (nn & 7) * 4;
    uint32_t b_sts1 = (uint32_t)(btile * 2 + 1) * 32 + (nn & 7) * 4;

    int mw = wid >> 2, nw = wid & 3;

    float acc[2][8][4];
#pragma unroll
    for (int mt = 0; mt < 2; ++mt)
#pragma unroll
        for (int nt = 0; nt < 8; ++nt)
#pragma unroll
            for (int q = 0; q < 4; ++q) acc[mt][nt][q] = 0.0f;

    float4 av0, av1, bv0, bv1, bv2, bv3;

#define F1_LDG(c) do { \
        av0 = *(const float4*)(Abase + (c) * 32); \
        av1 = *(const float4*)(Abase + (c) * 32 + 4); \
        bv0 = *(const float4*)(Bbase + (c) * 32); \
        bv1 = *(const float4*)(Bbase + (c) * 32 + 4); \
        bv2 = *(const float4*)(Bbase + (c) * 32 + 8); \
        bv3 = *(const float4*)(Bbase + (c) * 32 + 12); \
    } while (0)

#define F1_STS(st) do { \
        uint4 xa; \
        xa.x = pack_bf16(av0.x, av0.y); xa.y = pack_bf16(av0.z, av0.w); \
        xa.z = pack_bf16(av1.x, av1.y); xa.w = pack_bf16(av1.z, av1.w); \
        *(uint4*)&As_w0[(st) * 2048 + a_sts] = xa; \
        uint4 w0, w1; \
        w0.x = pack_bf16(bv0.x, bv0.y); w0.y = pack_bf16(bv0.z, bv0.w); \
        w0.z = pack_bf16(bv1.x, bv1.y); w0.w = pack_bf16(bv1.z, bv1.w); \
        w1.x = pack_bf16(bv2.x, bv2.y); w1.y = pack_bf16(bv2.z, bv2.w); \
        w1.z = pack_bf16(bv3.x, bv3.y); w1.w = pack_bf16(bv3.z, bv3.w); \
        *(uint4*)&Bs_w0[(st) * 4096 + b_sts0] = w0; \
        *(uint4*)&Bs_w0[(st) * 4096 + b_sts1] = w1; \
    } while (0)

    F1_LDG(0);
    F1_STS(0);
    F1_LDG(1);

    for (int c = 0; c < 8; ++c) {
        int st = c & 1;
        __syncthreads();
        const uint32_t* Asb = As_w0 + st * 2048;
        const uint32_t* Bsb = Bs_w0 + st * 4096;
#pragma unroll
        for (int ks = 0; ks < 2; ++ks) {
            uint32_t a[2][4];
#pragma unroll
            for (int mt = 0; mt < 2; ++mt) {
                int tile = (mw * 2 + mt) * 2 + ks;
#pragma unroll
                for (int rg = 0; rg < 4; ++rg)
                    a[mt][rg] = Asb[(tile * 4 + rg) * 32 + lid];
            }
#pragma unroll
            for (int nt = 0; nt < 8; ++nt) {
                int tile = (nw * 8 + nt) * 2 + ks;
                uint32_t b0 = Bsb[(tile * 2 + 0) * 32 + lid];
                uint32_t b1 = Bsb[(tile * 2 + 1) * 32 + lid];
                mma_bf16(acc[0][nt], a[0], b0, b1);
                mma_bf16(acc[1][nt], a[1], b0, b1);
            }
        }
        if (c < 7) {
            F1_STS((c + 1) & 1);
            if (c < 6) F1_LDG(c + 2);
        }
    }

    int lq = lid & 3, lr = lid >> 2;
    uint32_t* outp = g_hrhs + (size_t)(kk * 2 + half) * HH_PLANE;
#pragma unroll
    for (int mt = 0; mt < 2; ++mt)
#pragma unroll
        for (int rh = 0; rh < 2; ++rh) {
            int row = m0 + mw * 32 + mt * 16 + rh * 8 + lr;
#pragma unroll
            for (int nt = 0; nt < 8; ++nt) {
                int col = nw * 64 + nt * 8 + lq * 2;
                float v0 = acc[mt][nt][rh * 2 + 0] + biasS[col];
                float v1 = acc[mt][nt][rh * 2 + 1] + biasS[col + 1];
                outp[(size_t)row * HH_ROW_WORDS + (col >> 1)] = pack_bf16(v0, v1);
            }
        }
#undef F1_LDG
#undef F1_STS
}

// ---------------- gate GEMMs via bf16 mma (M128, grid (25,3) — measured best) ----------------
__global__ void __launch_bounds__(512, 1) gate_mma(
    const float* __restrict__ hr_w, const float* __restrict__ hi_w, const float* __restrict__ hh_w)
{
    extern __shared__ uint32_t dsm[];
    uint32_t* As_w0 = dsm;
    uint32_t* Bs_w0 = dsm + 4096;

    int t = threadIdx.x;
    int wid = t >> 5, lid = t & 31;
    int m0 = blockIdx.x * 128;
    int z = blockIdx.y;
    const float* W = (z == 0) ? hr_w : (z == 1) ? hi_w : hh_w;
    float* C = g_scratch + ((z == 0) ? GR_OFF : (z == 1) ? GI_OFF : GH_OFF);
    const float* A = g_scratch + AGG_OFF;

    int grow = t >> 2, kq = t & 3;
    int kstep = kq >> 1, khalf = kq & 1;
    int mtile = grow >> 4, rl = grow & 15;
    uint32_t a_sts = (uint32_t)(((mtile * 2 + kstep) * 4) + (rl >> 3) + 2 * khalf) * 32
                     + (rl & 7) * 4;
    const float* Abase = A + (size_t)(m0 + grow) * 256 + kq * 8;

    int nn = t >> 1, kh = t & 1;
    const float* Bbase = W + (size_t)nn * 256 + kh * 16;
    int btile = (nn >> 3) * 2 + kh;
    uint32_t b_sts0 = (uint32_t)(btile * 2 + 0) * 32 + (nn & 7) * 4;
    uint32_t b_sts1 = (uint32_t)(btile * 2 + 1) * 32 + (nn & 7) * 4;

    int mw = wid >> 2, nw = wid & 3;

    float acc[2][8][4];
#pragma unroll
    for (int mt = 0; mt < 2; ++mt)
#pragma unroll
        for (int nt = 0; nt < 8; ++nt)
#pragma unroll
            for (int q = 0; q < 4; ++q) acc[mt][nt][q] = 0.0f;

    float4 av0, av1, bv0, bv1, bv2, bv3;

#define G_LDG(c) do { \
        av0 = *(const float4*)(Abase + (c) * 32); \
        av1 = *(const float4*)(Abase + (c) * 32 + 4); \
        bv0 = *(const float4*)(Bbase + (c) * 32); \
        bv1 = *(const float4*)(Bbase + (c) * 32 + 4); \
        bv2 = *(const float4*)(Bbase + (c) * 32 + 8); \
        bv3 = *(const float4*)(Bbase + (c) * 32 + 12); \
    } while (0)

#define G_STS(st) do { \
        uint4 xa; \
        xa.x = pack_bf16(av0.x, av0.y); xa.y = pack_bf16(av0.z, av0.w); \
        xa.z = pack_bf16(av1.x, av1.y); xa.w = pack_bf16(av1.z, av1.w); \
        *(uint4*)&As_w0[(st) * 2048 + a_sts] = xa; \
        uint4 w0, w1; \
        w0.x = pack_bf16(bv0.x, bv0.y); w0.y = pack_bf16(bv0.z, bv0.w); \
        w0.z = pack_bf16(bv1.x, bv1.y); w0.w = pack_bf16(bv1.z, bv1.w); \
        w1.x = pack_bf16(bv2.x, bv2.y); w1.y = pack_bf16(bv2.z, bv2.w); \
        w1.z = pack_bf16(bv3.x, bv3.y); w1.w = pack_bf16(bv3.z, bv3.w); \
        *(uint4*)&Bs_w0[(st) * 4096 + b_sts0] = w0; \
        *(uint4*)&Bs_w0[(st) * 4096 + b_sts1] = w1; \
    } while (0)

    G_LDG(0);
    G_STS(0);
    G_LDG(1);

    for (int c = 0; c < 8; ++c) {
        int st = c & 1;
        __syncthreads();
        const uint32_t* Asb = As_w0 + st * 2048;
        const uint32_t* Bsb = Bs_w0 + st * 4096;
#pragma unroll
        for (int ks = 0; ks < 2; ++ks) {
            uint32_t a[2][4];
#pragma unroll
            for (int mt = 0; mt < 2; ++mt) {
                int tile = (mw * 2 + mt) * 2 + ks;
#pragma unroll
                for (int rg = 0; rg < 4; ++rg)
                    a[mt][rg] = Asb[(tile * 4 + rg) * 32 + lid];
            }
#pragma unroll
            for (int nt = 0; nt < 8; ++nt) {
                int tile = (nw * 8 + nt) * 2 + ks;
                uint32_t b0 = Bsb[(tile * 2 + 0) * 32 + lid];
                uint32_t b1 = Bsb[(tile * 2 + 1) * 32 + lid];
                mma_bf16(acc[0][nt], a[0], b0, b1);
                mma_bf16(acc[1][nt], a[1], b0, b1);
            }
        }
        if (c < 7) {
            G_STS((c + 1) & 1);
            if (c < 6) G_LDG(c + 2);
        }
    }

    int lq = lid & 3, lr = lid >> 2;
#pragma unroll
    for (int mt = 0; mt < 2; ++mt)
#pragma unroll
        for (int rh = 0; rh < 2; ++rh) {
            int row = m0 + mw * 32 + mt * 16 + rh * 8 + lr;
#pragma unroll
            for (int nt = 0; nt < 8; ++nt) {
                int col = nw * 64 + nt * 8 + lq * 2;
                C[(size_t)row * 256 + col]     = acc[mt][nt][rh * 2 + 0];
                C[(size_t)row * 256 + col + 1] = acc[mt][nt][rh * 2 + 1];
            }
        }
#undef G_LDG
#undef G_STS
}

// ---------------- GRU elementwise ----------------
__global__ void gru_elem(const float* __restrict__ hidden, float* __restrict__ new_hidden) {
    const float* tr = g_scratch + TR_OFF;
    const float* ti = g_scratch + TI_OFF;
    const float* tn = g_scratch + TN_OFF;
    const float* gr = g_scratch + GR_OFF;
    const float* gi = g_scratch + GI_OFF;
    const float* gh = g_scratch + GH_OFF;
    int total = BATCH * NVARS * NHID;
    for (int idx = blockIdx.x * blockDim.x + threadIdx.x; idx < total; idx += gridDim.x * blockDim.x) {
        float r_ = sigm(gr[idx] + tr[idx]);
        float i_ = sigm(gi[idx] + ti[idx]);
        float n_ = tanha(tn[idx] + r_ * gh[idx]);
        new_hidden[idx] = (1.0f - i_) * n_ + i_ * hidden[idx];
    }
}

// ---------------- head GEMM via split-bf16 (3-MMA), N128 per block, grid (25,2) ----------------
__global__ void __launch_bounds__(512, 1) head_mma(
    const float* __restrict__ Ain, const float* __restrict__ W,
    const float* __restrict__ bias, float* __restrict__ C)
{
    extern __shared__ uint32_t dsm[];
    uint32_t* Ahi = dsm;
    uint32_t* Alo = dsm + 2048;
    uint32_t* Bhi = dsm + 4096;
    uint32_t* Blo = dsm + 6144;
    float* biasS = (float*)(dsm + 8192);

    int t = threadIdx.x;
    int wid = t >> 5, lid = t & 31;
    int m0 = blockIdx.x * 128;
    int nh = blockIdx.y;

    if (t < 256) biasS[t] = bias[t];

    int grow = t >> 2, kq = t & 3;
    int kstep = kq >> 1, khalf = kq & 1;
    int mtile = grow >> 4, rl = grow & 15;
    uint32_t a_sts = (uint32_t)(((mtile * 2 + kstep) * 4) + (rl >> 3) + 2 * khalf) * 32
                     + (rl & 7) * 4;
    const float* Abase = Ain + (size_t)(m0 + grow) * 256 + kq * 8;

    int nn = t >> 2, khb = (t >> 1) & 1, sub = t & 1;
    const float* Bbase = W + (size_t)(nh * 128 + nn) * 256 + khb * 16 + sub * 8;
    int btile = (nn >> 3) * 2 + khb;
    uint32_t b_sts = (uint32_t)(btile * 2 + sub) * 32 + (nn & 7) * 4;

    int mw = wid >> 2, nw = wid & 3;

    float acc[2][4][4];
#pragma unroll
    for (int mt = 0; mt < 2; ++mt)
#pragma unroll
        for (int nt = 0; nt < 4; ++nt)
#pragma unroll
            for (int q = 0; q < 4; ++q) acc[mt][nt][q] = 0.0f;

    float4 av0, av1, bv0, bv1;

#define H_LDG(c) do { \
        av0 = *(const float4*)(Abase + (c) * 32); \
        av1 = *(const float4*)(Abase + (c) * 32 + 4); \
        bv0 = *(const float4*)(Bbase + (c) * 32); \
        bv1 = *(const float4*)(Bbase + (c) * 32 + 4); \
    } while (0)

#define H_STS() do { \
        uint4 xh, xl; \
        split_bf16(av0.x, av0.y, xh.x, xl.x); \
        split_bf16(av0.z, av0.w, xh.y, xl.y); \
        split_bf16(av1.x, av1.y, xh.z, xl.z); \
        split_bf16(av1.z, av1.w, xh.w, xl.w); \
        *(uint4*)&Ahi[a_sts] = xh; \
        *(uint4*)&Alo[a_sts] = xl; \
        uint4 wh, wl; \
        split_bf16(bv0.x, bv0.y, wh.x, wl.x); \
        split_bf16(bv0.z, bv0.w, wh.y, wl.y); \
        split_bf16(bv1.x, bv1.y, wh.z, wl.z); \
        split_bf16(bv1.z, bv1.w, wh.w, wl.w); \
        *(uint4*)&Bhi[b_sts] = wh; \
        *(uint4*)&Blo[b_sts] = wl; \
    } while (0)

    H_LDG(0);

    for (int c = 0; c < 8; ++c) {
        __syncthreads();
        H_STS();
        __syncthreads();
        if (c < 7) H_LDG(c + 1);
#pragma unroll
        for (int ks = 0; ks < 2; ++ks) {
            uint32_t ah[2][4], al[2][4];
#pragma unroll
            for (int mt = 0; mt < 2; ++mt) {
                int tile = (mw * 2 + mt) * 2 + ks;
#pragma unroll
                for (int rg = 0; rg < 4; ++rg) {
                    ah[mt][rg] = Ahi[(tile * 4 + rg) * 32 + lid];
                    al[mt][rg] = Alo[(tile * 4 + rg) * 32 + lid];
                }
            }
#pragma unroll
            for (int nt = 0; nt < 4; ++nt) {
                int tile = (nw * 4 + nt) * 2 + ks;
                uint32_t bh0 = Bhi[(tile * 2 + 0) * 32 + lid];
                uint32_t bh1 = Bhi[(tile * 2 + 1) * 32 + lid];
                uint32_t bl0 = Blo[(tile * 2 + 0) * 32 + lid];
                uint32_t bl1 = Blo[(tile * 2 + 1) * 32 + lid];
#pragma unroll
                for (int mt = 0; mt < 2; ++mt) {
                    mma_bf16(acc[mt][nt], ah[mt], bh0, bh1);
                    mma_bf16(acc[mt][nt], ah[mt], bl0, bl1);
                    mma_bf16(acc[mt][nt], al[mt], bh0, bh1);
                }
            }
        }
    }

    int lq = lid & 3, lr = lid >> 2;
#pragma unroll
    for (int mt = 0; mt < 2; ++mt)
#pragma unroll
        for (int rh = 0; rh < 2; ++rh) {
            int row = m0 + mw * 32 + mt * 16 + rh * 8 + lr;
#pragma unroll
            for (int nt = 0; nt < 4; ++nt) {
                int colg = nh * 128 + nw * 32 + nt * 8 + lq * 2;
                float v0 = fmaxf(acc[mt][nt][rh * 2 + 0] + biasS[colg], 0.0f);
                float v1 = fmaxf(acc[mt][nt][rh * 2 + 1] + biasS[colg + 1], 0.0f);
                C[(size_t)row * 256 + colg]     = v0;
                C[(size_t)row * 256 + colg + 1] = v1;
            }
        }
#undef H_LDG
#undef H_STS
}

// ---------------- bf16 mma.sync edge kernel: W resident in smem, 5 receivers/block ----------------
// grid (25, 10, 3): x = m-tile (128 rows), y = receiver group (r = 5y..5y+4), z = kk.
__global__ void __launch_bounds__(512, 1) edge_mma(
    const float* __restrict__ edges,
    const float* __restrict__ fc2b)
{
    extern __shared__ uint32_t dsm[];
    uint32_t* Ws = dsm;                 // 8x4096 (full W, resident)
    uint32_t* As_w0 = dsm + 32768;      // 2x2048
    float* biasS = (float*)(dsm + 32768 + 4096);

    int t = threadIdx.x;
    int wid = t >> 5, lid = t & 31;
    int m0 = blockIdx.x * 128;
    int r0 = blockIdx.y * 5;
    int kk = blockIdx.z, kt = kk + 1;

    const uint32_t* HRw = g_hrhs + (size_t)(kk * 2 + 0) * HH_PLANE;
    const uint32_t* HSw = g_hrhs + (size_t)(kk * 2 + 1) * HH_PLANE;

    if (t < 256) biasS[t] = fc2b[kt * 256 + t];

    int grow = t >> 2, kq = t & 3;
    int kstep = kq >> 1, khalf = kq & 1;
    int gg = m0 + grow;
    int gb = gg / 50, gi = gg - gb * 50;
    uint32_t hs_base = (uint32_t)(gb * 50 + gi) * HH_ROW_WORDS + kq * 4;
    int mtile = grow >> 4, rl = grow & 15;
    uint32_t a_sts = (uint32_t)(((mtile * 2 + kstep) * 4) + (rl >> 3) + 2 * khalf) * 32
                     + (rl & 7) * 4;
    const uint32_t* wf = g_wf + (size_t)kk * 32768 + t * 8;
    uint32_t ws_u32 = (uint32_t)__cvta_generic_to_shared(Ws) + t * 8 * 4;

    int mw = wid >> 2, nw = wid & 3;

    // issue the full W load (8 chunk-groups, committed in order)
#pragma unroll
    for (int c = 0; c < 8; ++c) {
        uint32_t d = ws_u32 + c * 4096 * 4;
        CP16(d, wf + c * 4096);
        CP16(d + 16, wf + c * 4096 + 4);
        CP_COMMIT();
    }

    // epilogue row mapping (r-independent)
    int lq = lid & 3, lr = lid >> 2;
    int base_row = mw * 32;
    int bfirst = (m0 + base_row) / 50;
    int blast = (m0 + base_row + 31) / 50;
    int has1 = (blast != bfirst);
    int erow_b[4], erow_i[4], sg[4];
#pragma unroll
    for (int j = 0; j < 4; ++j) {
        int mt = j >> 1, rh = j & 1;
        int g = m0 + base_row + mt * 16 + rh * 8 + lr;
        erow_b[j] = g / 50;
        erow_i[j] = g - erow_b[j] * 50;
        sg[j] = erow_b[j] - bfirst;
    }

    uint4 hv, sv;
    uint32_t hr_base;

#define LDG_A(c) do { \
        hv = *(const uint4*)(HRw + hr_base + (c) * 16); \
        sv = *(const uint4*)(HSw + hs_base + (c) * 16); \
    } while (0)

#define STS_A(st) do { \
        uint4 xa; \
        xa.x = tanh_bf16x2(add_bf16x2(hv.x, sv.x)); \
        xa.y = tanh_bf16x2(add_bf16x2(hv.y, sv.y)); \
        xa.z = tanh_bf16x2(add_bf16x2(hv.z, sv.z)); \
        xa.w = tanh_bf16x2(add_bf16x2(hv.w, sv.w)); \
        *(uint4*)&As_w0[(st) * 2048 + a_sts] = xa; \
    } while (0)

    for (int rl5 = 0; rl5 < 5; ++rl5) {
        int r = r0 + rl5;
        hr_base = (uint32_t)(gb * 50 + r) * HH_ROW_WORDS + kq * 4;

        float acc[2][8][4];
#pragma unroll
        for (int mt = 0; mt < 2; ++mt)
#pragma unroll
            for (int nt = 0; nt < 8; ++nt)
#pragma unroll
                for (int q = 0; q < 4; ++q) acc[mt][nt][q] = 0.0f;

        LDG_A(0);
        STS_A(0);
        LDG_A(1);

#pragma unroll
        for (int c = 0; c < 8; ++c) {
            if (rl5 == 0) {
                switch (c) {
                    case 0: CP_WAIT(7); break;
                    case 1: CP_WAIT(6); break;
                    case 2: CP_WAIT(5); break;
                    case 3: CP_WAIT(4); break;
                    case 4: CP_WAIT(3); break;
                    case 5: CP_WAIT(2); break;
                    case 6: CP_WAIT(1); break;
                    case 7: CP_WAIT(0); break;
                }
            }
            __syncthreads();
            const uint32_t* Asb = As_w0 + (c & 1) * 2048;
            const uint32_t* Bsb = Ws + c * 4096;
#pragma unroll
            for (int ks = 0; ks < 2; ++ks) {
                uint32_t a[2][4];
#pragma unroll
                for (int mt = 0; mt < 2; ++mt) {
                    int tile = (mw * 2 + mt) * 2 + ks;
#pragma unroll
                    for (int rg = 0; rg < 4; ++rg)
                        a[mt][rg] = Asb[(tile * 4 + rg) * 32 + lid];
                }
#pragma unroll
                for (int nt = 0; nt < 8; ++nt) {
                    int tile = (nw * 8 + nt) * 2 + ks;
                    uint32_t b0 = Bsb[(tile * 2 + 0) * 32 + lid];
                    uint32_t b1 = Bsb[(tile * 2 + 1) * 32 + lid];
                    mma_bf16(acc[0][nt], a[0], b0, b1);
                    mma_bf16(acc[1][nt], a[1], b0, b1);
                }
            }
            if (c < 7) {
                STS_A((c + 1) & 1);
                if (c < 6) LDG_A(c + 2);
            }
        }

        // epilogue for this r
        float wgt[4];
#pragma unroll
        for (int j = 0; j < 4; ++j) {
            float w = 0.0f;
            int i = erow_i[j];
            if (i != r) {
                int e = i * 49 + r - (i < r ? 1 : 0);
                w = __ldg(&edges[((size_t)erow_b[j] * NEDGE + e) * 4 + kt]) * (1.0f / 147.0f);
            }
            wgt[j] = w;
        }

        float* agg0 = g_scratch + AGG_OFF + ((size_t)(bfirst * 50 + r)) * 256;

#pragma unroll
        for (int nt = 0; nt < 8; ++nt) {
            int colg = nw * 64 + nt * 8 + lq * 2;
            float b0 = biasS[colg], b1 = biasS[colg + 1];
            float c0[2] = {0.0f, 0.0f}, c1[2] = {0.0f, 0.0f};
#pragma unroll
            for (int j = 0; j < 4; ++j) {
                int mt = j >> 1, rh = j & 1;
                float t0 = tanha(acc[mt][nt][rh * 2 + 0] + b0) * wgt[j];
                float t1 = tanha(acc[mt][nt][rh * 2 + 1] + b1) * wgt[j];
                if (sg[j] == 0) { c0[0] += t0; c1[0] += t1; }
                else            { c0[1] += t0; c1[1] += t1; }
            }
#pragma unroll
            for (int o = 4; o <= 16; o <<= 1) {
                c0[0] += __shfl_xor_sync(0xffffffffu, c0[0], o);
                c1[0] += __shfl_xor_sync(0xffffffffu, c1[0], o);
                if (has1) {
                    c0[1] += __shfl_xor_sync(0xffffffffu, c0[1], o);
                    c1[1] += __shfl_xor_sync(0xffffffffu, c1[1], o);
                }
            }
            if (lid < 4) {
                atomicAdd(&agg0[colg], c0[0]);
                atomicAdd(&agg0[colg + 1], c1[0]);
                if (has1) {
                    atomicAdd(&agg0[12800 + colg], c0[1]);
                    atomicAdd(&agg0[12800 + colg + 1], c1[1]);
                }
            }
        }
    }
#undef LDG_A
#undef STS_A
}

// ---------------- launch ----------------
extern "C" void kernel_launch(void* const* d_in, const int* in_sizes, int n_in,
                              void* d_out, int out_size) {
    const float* inputs = (const float*)d_in[0];
    const float* hidden = (const float*)d_in[1];
    const float* edges  = (const float*)d_in[2];
    const float* fc1w   = (const float*)d_in[3];
    const float* fc1b   = (const float*)d_in[4];
    const float* fc2w   = (const float*)d_in[5];
    const float* fc2b   = (const float*)d_in[6];
    const float* hr_w   = (const float*)d_in[7];
    const float* hi_w   = (const float*)d_in[8];
    const float* hh_w   = (const float*)d_in[9];
    const float* ir_w   = (const float*)d_in[10];
    const float* ir_b   = (const float*)d_in[11];
    const float* ii_w   = (const float*)d_in[12];
    const float* ii_b   = (const float*)d_in[13];
    const float* in_w   = (const float*)d_in[14];
    const float* in_b   = (const float*)d_in[15];
    const float* of1_w  = (const float*)d_in[16];
    const float* of1_b  = (const float*)d_in[17];
    const float* of2_w  = (const float*)d_in[18];
    const float* of2_b  = (const float*)d_in[19];
    const float* mu_w   = (const float*)d_in[20];
    const float* mu_b   = (const float*)d_in[21];

    float* out = (float*)d_out;
    float* out_mu   = out;               // [64,50,64]
    float* out_nh   = out + 204800;      // [64,50,256]
    float* out_pred = out + 1024000;     // [64,50,256]

    float* S = nullptr;
    cudaGetSymbolAddress((void**)&S, g_scratch);

    cudaFuncSetAttribute(edge_mma, cudaFuncAttributeMaxDynamicSharedMemorySize, EDGE_SMEM_BYTES);
    cudaFuncSetAttribute(fc1_mma, cudaFuncAttributeMaxDynamicSharedMemorySize, BIG_SMEM_BYTES);
    cudaFuncSetAttribute(gate_mma, cudaFuncAttributeMaxDynamicSharedMemorySize, BIG_SMEM_BYTES);
    cudaFuncSetAttribute(head_mma, cudaFuncAttributeMaxDynamicSharedMemorySize, HEAD_SMEM_BYTES);

    const int M = BATCH * NVARS;  // 3200

    fc1_mma<<<dim3(25, 3, 2), 512, BIG_SMEM_BYTES>>>(hidden, fc1w, fc1b);
    pre_all<<<1192, 128>>>(inputs, ir_w, ii_w, in_w, ir_b, ii_b, in_b, fc2w);

    edge_mma<<<dim3(25, 10, 3), 512, EDGE_SMEM_BYTES>>>(edges, fc2b);

    gate_mma<<<dim3(25, 3), 512, BIG_SMEM_BYTES>>>(hr_w, hi_w, hh_w);
    gru_elem<<<800, 256>>>(hidden, out_nh);

    head_mma<<<dim3(25, 2), 512, HEAD_SMEM_BYTES>>>(out_nh, of1_w, of1_b, S + P1_OFF);
    head_mma<<<dim3(25, 2), 512, HEAD_SMEM_BYTES>>>(S + P1_OFF, of2_w, of2_b, out_pred);

    gemm_nt<0><<<dim3(M / 64, 1), 128>>>(out_pred, NHID, mu_w, NHID, mu_b, out_mu, NIN, NHID);
}